// round 8
// baseline (speedup 1.0000x reference)
#include <cuda_runtime.h>

#define DEV __device__ __forceinline__

__constant__ float c_mean[3] = {0.485f, 0.456f, 0.406f};
__constant__ float c_std[3]  = {0.229f, 0.224f, 0.225f};

DEV void cas(float &a, float &b) { float t = fminf(a, b); b = fmaxf(a, b); a = t; }

// 16-CAS sort of 7.
DEV void sort7(float* x) {
    cas(x[0], x[1]); cas(x[2], x[3]); cas(x[0], x[2]); cas(x[1], x[3]); cas(x[1], x[2]);
    cas(x[4], x[5]); cas(x[4], x[6]); cas(x[5], x[6]);
    cas(x[0], x[4]); cas(x[1], x[5]); cas(x[2], x[6]);
    cas(x[2], x[4]); cas(x[3], x[5]);
    cas(x[1], x[2]); cas(x[3], x[4]); cas(x[5], x[6]);
}

// Pruned Batcher merge of sorted a[7], b[7] -> sorted x[0..13]. 21 CAS.
DEV void merge77(const float* a, const float* b, float* x /*>=15*/) {
    #pragma unroll
    for (int i = 0; i < 7; ++i) x[i] = a[i];
    #pragma unroll
    for (int i = 0; i < 7; ++i) x[8 + i] = b[i];
    cas(x[0], x[8]); cas(x[1], x[9]); cas(x[2], x[10]); cas(x[3], x[11]);
    cas(x[4], x[12]); cas(x[5], x[13]); cas(x[6], x[14]);
    x[7] = x[11];
    cas(x[4], x[8]); cas(x[5], x[9]); cas(x[6], x[10]);
    cas(x[2], x[4]); cas(x[3], x[5]); cas(x[6], x[8]); cas(x[7], x[9]);
    cas(x[10], x[12]); x[11] = x[13];
    cas(x[1], x[2]); cas(x[3], x[4]); cas(x[5], x[6]); cas(x[7], x[8]);
    cas(x[9], x[10]); cas(x[11], x[12]); x[13] = x[14];
}

// Pruned merge of sorted A[14], B[14] -> x with ranks 3..24 valid. 53 CAS.
DEV void build_S(const float* A, const float* B, float* x /*>=30*/) {
    #pragma unroll
    for (int i = 0; i < 14; ++i) x[i] = A[i];
    #pragma unroll
    for (int i = 0; i < 14; ++i) x[16 + i] = B[i];
    #pragma unroll
    for (int i = 0; i < 14; ++i) cas(x[i], x[i + 16]);
    cas(x[8], x[16]); cas(x[9], x[17]); cas(x[10], x[18]);
    cas(x[11], x[19]); cas(x[12], x[20]); cas(x[13], x[21]);
    x[14] = x[22]; x[15] = x[23];
    cas(x[4], x[8]); cas(x[5], x[9]); cas(x[6], x[10]); cas(x[7], x[11]);
    cas(x[12], x[16]); cas(x[13], x[17]); cas(x[14], x[18]); cas(x[15], x[19]);
    cas(x[20], x[24]); cas(x[21], x[25]);
    x[22] = x[26]; x[23] = x[27];
    cas(x[2], x[4]);  cas(x[3], x[5]);  cas(x[6], x[8]);  cas(x[7], x[9]);
    cas(x[10], x[12]); cas(x[11], x[13]); cas(x[14], x[16]); cas(x[15], x[17]);
    cas(x[18], x[20]); cas(x[19], x[21]); cas(x[22], x[24]); cas(x[23], x[25]);
    cas(x[3], x[4]);  cas(x[5], x[6]);  cas(x[7], x[8]);  cas(x[9], x[10]);
    cas(x[11], x[12]); cas(x[13], x[14]); cas(x[15], x[16]); cas(x[17], x[18]);
    cas(x[19], x[20]); cas(x[21], x[22]); cas(x[23], x[24]);
}

// E = pruned merge of sorted C[14], sorted g[7]; ranks E[0..20] valid (39 CAS).
// Then rank-25 of S(28) U E(21) via split identity with 4 rotating accumulators.
DEV float final_select(const float* S, const float* C, const float* g) {
    float x[23];
    #pragma unroll
    for (int i = 0; i < 14; ++i) x[i] = C[i];
    #pragma unroll
    for (int i = 0; i < 7; ++i) x[16 + i] = g[i];
    cas(x[0], x[16]); cas(x[1], x[17]); cas(x[2], x[18]); cas(x[3], x[19]);
    cas(x[4], x[20]); cas(x[5], x[21]); cas(x[6], x[22]);
    cas(x[8], x[16]); cas(x[9], x[17]); cas(x[10], x[18]);
    cas(x[11], x[19]); cas(x[12], x[20]); cas(x[13], x[21]);
    x[14] = x[22];
    cas(x[4], x[8]); cas(x[5], x[9]); cas(x[6], x[10]); cas(x[7], x[11]);
    cas(x[12], x[16]); cas(x[13], x[17]); cas(x[14], x[18]);
    x[15] = x[19];
    cas(x[2], x[4]);  cas(x[3], x[5]);  cas(x[6], x[8]);  cas(x[7], x[9]);
    cas(x[10], x[12]); cas(x[11], x[13]); cas(x[14], x[16]); cas(x[15], x[17]);
    cas(x[18], x[20]);
    x[19] = x[21];
    cas(x[1], x[2]);  cas(x[3], x[4]);  cas(x[5], x[6]);  cas(x[7], x[8]);
    cas(x[9], x[10]); cas(x[11], x[12]); cas(x[13], x[14]); cas(x[15], x[16]);
    cas(x[17], x[18]); cas(x[19], x[20]);
    // med = min(S[24], min_{i=4..24} max(S[i-1], E[24-i])), 4 accumulators
    float a0 = S[24];
    float a1 = fmaxf(S[3], x[20]);
    float a2 = fmaxf(S[4], x[19]);
    float a3 = fmaxf(S[5], x[18]);
    #pragma unroll
    for (int i = 7; i <= 24; ++i) {
        float m = fmaxf(S[i - 1], x[24 - i]);
        switch ((i - 3) & 3) {
            case 0: a0 = fminf(a0, m); break;
            case 1: a1 = fminf(a1, m); break;
            case 2: a2 = fminf(a2, m); break;
            default: a3 = fminf(a3, m); break;
        }
    }
    return fminf(fminf(a0, a1), fminf(a2, a3));
}

DEV void load_pair(const float4 (*pb)[5], int m, float* P) {
    float4 v0 = pb[m][0], v1 = pb[m][1], v2 = pb[m][2], v3 = pb[m][3];
    P[0] = v0.x;  P[1] = v0.y;  P[2]  = v0.z;  P[3]  = v0.w;
    P[4] = v1.x;  P[5] = v1.y;  P[6]  = v1.z;  P[7]  = v1.w;
    P[8] = v2.x;  P[9] = v2.y;  P[10] = v2.z;  P[11] = v2.w;
    P[12] = v3.x; P[13] = v3.y;
}

// One CTA = one output row of one (b,c) plane; 256 threads x 2 px.
__global__ __launch_bounds__(256, 4) void median7_kernel(const float* __restrict__ img,
                                                         float* __restrict__ out) {
    const int y     = blockIdx.x;        // 0..511
    const int plane = blockIdx.y;        // 0..23
    const int ch    = plane % 3;
    const float mean = c_mean[ch];
    const float sd   = c_std[ch];

    __shared__ float  srow[7][518];      // rows -> sorted columns (in place)
    __shared__ float4 pairbuf[260][5];   // pair m: sorted 14 in [m][0..3]

    const float* src = img + (size_t)plane * 262144;

    #pragma unroll
    for (int r = 0; r < 7; ++r) {
        int gy = y + r - 3;
        gy = (gy < 0) ? -gy : ((gy > 511) ? 1022 - gy : gy);
        const float* rp = src + gy * 512;
        for (int c = threadIdx.x; c < 518; c += 256) {
            int gx = c - 3;
            gx = (gx < 0) ? -gx : ((gx > 511) ? 1022 - gx : gx);
            float v = fmaf(rp[gx], sd, mean);
            srow[r][c] = fminf(fmaxf(v, 0.0f), 1.0f);
        }
    }
    __syncthreads();

    // Phase 1: task m owns smem columns 2m, 2m+1 exclusively (m < 259).
    for (int m = threadIdx.x; m < 259; m += 256) {
        float ca[7], cb[7], x[15];
        #pragma unroll
        for (int d = 0; d < 7; ++d) { ca[d] = srow[d][2 * m]; cb[d] = srow[d][2 * m + 1]; }
        sort7(ca); sort7(cb);
        #pragma unroll
        for (int d = 0; d < 7; ++d) { srow[d][2 * m] = ca[d]; srow[d][2 * m + 1] = cb[d]; }
        merge77(ca, cb, x);              // x[0..13] sorted
        pairbuf[m][0] = make_float4(x[0],  x[1],  x[2],  x[3]);
        pairbuf[m][1] = make_float4(x[4],  x[5],  x[6],  x[7]);
        pairbuf[m][2] = make_float4(x[8],  x[9],  x[10], x[11]);
        pairbuf[m][3] = make_float4(x[12], x[13], 0.0f,  0.0f);
    }
    __syncthreads();

    const int t = threadIdx.x;           // px0 global col = 2t

    // Prefetch px0's E inputs so their LDS latency hides under build_S math.
    float C0[14], g0[7];
    load_pair(pairbuf, t, C0);
    #pragma unroll
    for (int d = 0; d < 7; ++d) g0[d] = srow[d][2 * t + 6];

    // S = merge(pair t+1, pair t+2): shared by px0 and px1.
    float S[30];
    {
        float P1[14], P2[14];
        load_pair(pairbuf, t + 1, P1);
        load_pair(pairbuf, t + 2, P2);
        build_S(P1, P2, S);
    }

    float m0 = final_select(S, C0, g0);  // px0: E(pair t, lone smem col 2t+6)

    float m1;
    {   // px1: E(pair t+3, lone smem col 2t+1)
        float C[14], g[7];
        load_pair(pairbuf, t + 3, C);
        #pragma unroll
        for (int d = 0; d < 7; ++d) g[d] = srow[d][2 * t + 1];
        m1 = final_select(S, C, g);
    }

    const float inv = 1.0f / sd;
    float2 o;
    o.x = (m0 - mean) * inv;
    o.y = (m1 - mean) * inv;
    *reinterpret_cast<float2*>(out + (size_t)plane * 262144 + y * 512 + 2 * t) = o;
}

extern "C" void kernel_launch(void* const* d_in, const int* in_sizes, int n_in,
                              void* d_out, int out_size) {
    const float* img  = (const float*)d_in[0];
    const float* mask = (const float*)d_in[1];
    float* out = (float*)d_out;
    const int img_elems  = in_sizes[0];
    const int mask_elems = in_sizes[1];

    dim3 grid(512, 24);
    median7_kernel<<<grid, 256>>>(img, out);
    cudaMemcpyAsync(out + img_elems, mask, (size_t)mask_elems * sizeof(float),
                    cudaMemcpyDeviceToDevice);
}

// round 9
// speedup vs baseline: 1.1190x; 1.1190x over previous
#include <cuda_runtime.h>

#define DEV __device__ __forceinline__
#define BIG 1.0e30f

__constant__ float c_mean[3] = {0.485f, 0.456f, 0.406f};
__constant__ float c_std[3]  = {0.229f, 0.224f, 0.225f};

DEV void cas(float &a, float &b) { float t = fminf(a, b); b = fmaxf(a, b); a = t; }

// 16-CAS sort of 7.
DEV void sort7(float* x) {
    cas(x[0], x[1]); cas(x[2], x[3]); cas(x[0], x[2]); cas(x[1], x[3]); cas(x[1], x[2]);
    cas(x[4], x[5]); cas(x[4], x[6]); cas(x[5], x[6]);
    cas(x[0], x[4]); cas(x[1], x[5]); cas(x[2], x[6]);
    cas(x[2], x[4]); cas(x[3], x[5]);
    cas(x[1], x[2]); cas(x[3], x[4]); cas(x[5], x[6]);
}

// Pruned Batcher merge of sorted a[7], b[7] -> sorted x[0..13]. 21 CAS.
DEV void merge77(const float* a, const float* b, float* x /*>=15*/) {
    #pragma unroll
    for (int i = 0; i < 7; ++i) x[i] = a[i];
    #pragma unroll
    for (int i = 0; i < 7; ++i) x[8 + i] = b[i];
    cas(x[0], x[8]); cas(x[1], x[9]); cas(x[2], x[10]); cas(x[3], x[11]);
    cas(x[4], x[12]); cas(x[5], x[13]); cas(x[6], x[14]);
    x[7] = x[11];
    cas(x[4], x[8]); cas(x[5], x[9]); cas(x[6], x[10]);
    cas(x[2], x[4]); cas(x[3], x[5]); cas(x[6], x[8]); cas(x[7], x[9]);
    cas(x[10], x[12]); x[11] = x[13];
    cas(x[1], x[2]); cas(x[3], x[4]); cas(x[5], x[6]); cas(x[7], x[8]);
    cas(x[9], x[10]); cas(x[11], x[12]); x[13] = x[14];
}

// Full merge of sorted x[0..13] (A, with x[14]=x[15]=BIG) and sorted x[16..29] (B)
// -> M[0..27] in x[0..27].  oem(30,16) with sentinel renames. 55 CAS + 6 renames.
DEV void mergeM(float* x) {
    // K=16
    cas(x[0], x[16]); cas(x[1], x[17]); cas(x[2], x[18]); cas(x[3], x[19]);
    cas(x[4], x[20]); cas(x[5], x[21]); cas(x[6], x[22]); cas(x[7], x[23]);
    cas(x[8], x[24]); cas(x[9], x[25]); cas(x[10], x[26]); cas(x[11], x[27]);
    cas(x[12], x[28]); cas(x[13], x[29]);
    // K=8 (sentinels 14,15 -> renames)
    cas(x[8], x[16]); cas(x[9], x[17]); cas(x[10], x[18]);
    cas(x[11], x[19]); cas(x[12], x[20]); cas(x[13], x[21]);
    x[14] = x[22]; x[15] = x[23];
    // K=4 (22,23 now sentinel -> renames)
    cas(x[4], x[8]); cas(x[5], x[9]); cas(x[6], x[10]); cas(x[7], x[11]);
    cas(x[12], x[16]); cas(x[13], x[17]); cas(x[14], x[18]); cas(x[15], x[19]);
    cas(x[20], x[24]); cas(x[21], x[25]);
    x[22] = x[26]; x[23] = x[27];
    // K=2 (26,27 now sentinel -> renames)
    cas(x[2], x[4]);  cas(x[3], x[5]);  cas(x[6], x[8]);  cas(x[7], x[9]);
    cas(x[10], x[12]); cas(x[11], x[13]); cas(x[14], x[16]); cas(x[15], x[17]);
    cas(x[18], x[20]); cas(x[19], x[21]); cas(x[22], x[24]); cas(x[23], x[25]);
    x[26] = x[28]; x[27] = x[29];
    // K=1
    cas(x[1], x[2]);  cas(x[3], x[4]);  cas(x[5], x[6]);  cas(x[7], x[8]);
    cas(x[9], x[10]); cas(x[11], x[12]); cas(x[13], x[14]); cas(x[15], x[16]);
    cas(x[17], x[18]); cas(x[19], x[20]); cas(x[21], x[22]); cas(x[23], x[24]);
    cas(x[25], x[26]);
}

// Pruned merge of M[0..27] (in x[0..27]) with sorted x[32..45] (third pair),
// producing ONLY ranks 17..24 of the 42-merge in x[17..24].
// Cone-pruned oem(46,32): 53 CAS. x[28..31] never read.
DEV void mergeT(float* x) {
    // K=32
    cas(x[0], x[32]); cas(x[1], x[33]); cas(x[2], x[34]); cas(x[3], x[35]);
    cas(x[4], x[36]); cas(x[5], x[37]); cas(x[6], x[38]); cas(x[7], x[39]);
    cas(x[8], x[40]); cas(x[9], x[41]); cas(x[10], x[42]); cas(x[11], x[43]);
    cas(x[12], x[44]); cas(x[13], x[45]);
    // K=16
    cas(x[16], x[32]); cas(x[17], x[33]); cas(x[18], x[34]); cas(x[19], x[35]);
    cas(x[20], x[36]); cas(x[21], x[37]); cas(x[22], x[38]); cas(x[23], x[39]);
    cas(x[24], x[40]); cas(x[25], x[41]); cas(x[26], x[42]); cas(x[27], x[43]);
    // K=8 (cone)
    cas(x[9], x[17]); cas(x[10], x[18]); cas(x[11], x[19]); cas(x[12], x[20]);
    cas(x[13], x[21]); cas(x[14], x[22]); cas(x[15], x[23]);
    cas(x[24], x[32]); cas(x[25], x[33]); cas(x[26], x[34]); cas(x[27], x[35]);
    // K=4 (cone)
    cas(x[13], x[17]); cas(x[14], x[18]); cas(x[15], x[19]);
    cas(x[20], x[24]); cas(x[21], x[25]); cas(x[22], x[26]); cas(x[23], x[27]);
    // K=2 (cone)
    cas(x[15], x[17]); cas(x[18], x[20]); cas(x[19], x[21]);
    cas(x[22], x[24]); cas(x[23], x[25]);
    // K=1 (cone)
    cas(x[17], x[18]); cas(x[19], x[20]); cas(x[21], x[22]); cas(x[23], x[24]);
}

// med = rank 25 of T(42) U g(7) = min(T[24], min_j max(T[17+j], g[6-j])).
DEV float select25(const float* T, const float* g) {
    float c0 = fmaxf(T[17], g[6]);
    float c1 = fmaxf(T[18], g[5]);
    float c2 = fmaxf(T[19], g[4]);
    float c3 = fmaxf(T[20], g[3]);
    float c4 = fmaxf(T[21], g[2]);
    float c5 = fmaxf(T[22], g[1]);
    float c6 = fmaxf(T[23], g[0]);
    float c7 = T[24];
    return fminf(fminf(fminf(c0, c1), fminf(c2, c3)),
                 fminf(fminf(c4, c5), fminf(c6, c7)));
}

// One CTA = one output row of one (b,c) plane; 256 threads, 257 tasks x 2 px.
__global__ __launch_bounds__(256, 4) void median7_kernel(const float* __restrict__ img,
                                                         float* __restrict__ out) {
    const int y     = blockIdx.x;        // 0..511
    const int plane = blockIdx.y;        // 0..23
    const int ch    = plane % 3;
    const float mean = c_mean[ch];
    const float sd   = c_std[ch];

    __shared__ float  srow[7][518];      // rows -> sorted columns (in place)
    __shared__ float4 pairbuf[260][5];   // pair m: sorted 14 in [m][0..3]

    const float* src = img + (size_t)plane * 262144;

    #pragma unroll
    for (int r = 0; r < 7; ++r) {
        int gy = y + r - 3;
        gy = (gy < 0) ? -gy : ((gy > 511) ? 1022 - gy : gy);
        const float* rp = src + gy * 512;
        for (int c = threadIdx.x; c < 518; c += 256) {
            int gx = c - 3;
            gx = (gx < 0) ? -gx : ((gx > 511) ? 1022 - gx : gx);
            float v = fmaf(rp[gx], sd, mean);
            srow[r][c] = fminf(fmaxf(v, 0.0f), 1.0f);
        }
    }
    __syncthreads();

    // Phase 1: task m owns smem columns 2m, 2m+1 exclusively (m < 259).
    for (int m = threadIdx.x; m < 259; m += 256) {
        float ca[7], cb[7], w[15];
        #pragma unroll
        for (int d = 0; d < 7; ++d) { ca[d] = srow[d][2 * m]; cb[d] = srow[d][2 * m + 1]; }
        sort7(ca); sort7(cb);
        #pragma unroll
        for (int d = 0; d < 7; ++d) { srow[d][2 * m] = ca[d]; srow[d][2 * m + 1] = cb[d]; }
        merge77(ca, cb, w);              // w[0..13] sorted
        pairbuf[m][0] = make_float4(w[0],  w[1],  w[2],  w[3]);
        pairbuf[m][1] = make_float4(w[4],  w[5],  w[6],  w[7]);
        pairbuf[m][2] = make_float4(w[8],  w[9],  w[10], w[11]);
        pairbuf[m][3] = make_float4(w[12], w[13], 0.0f,  0.0f);
    }
    __syncthreads();

    const float inv = 1.0f / sd;
    float* orow = out + (size_t)plane * 262144 + y * 512;

    // Phase 2: task u covers pixels at global cols (2u-1, 2u); both share the
    // pair triple {u, u+1, u+2}. u=0 emits only col 0; u=256 only col 511.
    for (int u = threadIdx.x; u <= 256; u += 256) {
        float x[46];
        {   // pair u -> x[0..13]
            float4 v0 = pairbuf[u][0], v1 = pairbuf[u][1];
            float4 v2 = pairbuf[u][2], v3 = pairbuf[u][3];
            x[0]=v0.x; x[1]=v0.y; x[2]=v0.z; x[3]=v0.w;
            x[4]=v1.x; x[5]=v1.y; x[6]=v1.z; x[7]=v1.w;
            x[8]=v2.x; x[9]=v2.y; x[10]=v2.z; x[11]=v2.w;
            x[12]=v3.x; x[13]=v3.y;
        }
        x[14] = BIG; x[15] = BIG;
        {   // pair u+1 -> x[16..29]
            float4 v0 = pairbuf[u+1][0], v1 = pairbuf[u+1][1];
            float4 v2 = pairbuf[u+1][2], v3 = pairbuf[u+1][3];
            x[16]=v0.x; x[17]=v0.y; x[18]=v0.z; x[19]=v0.w;
            x[20]=v1.x; x[21]=v1.y; x[22]=v1.z; x[23]=v1.w;
            x[24]=v2.x; x[25]=v2.y; x[26]=v2.z; x[27]=v2.w;
            x[28]=v3.x; x[29]=v3.y;
        }
        mergeM(x);                       // x[0..27] = sorted 28
        {   // pair u+2 -> x[32..45]
            float4 v0 = pairbuf[u+2][0], v1 = pairbuf[u+2][1];
            float4 v2 = pairbuf[u+2][2], v3 = pairbuf[u+2][3];
            x[32]=v0.x; x[33]=v0.y; x[34]=v0.z; x[35]=v0.w;
            x[36]=v1.x; x[37]=v1.y; x[38]=v1.z; x[39]=v1.w;
            x[40]=v2.x; x[41]=v2.y; x[42]=v2.z; x[43]=v2.w;
            x[44]=v3.x; x[45]=v3.y;
        }
        mergeT(x);                       // x[17..24] = T[17..24]

        {   // odd pixel: global col 2u-1, lone sorted column smem 2u-1
            int gc = (2 * u - 1 < 0) ? 0 : 2 * u - 1;   // clamp; store predicated
            float g[7];
            #pragma unroll
            for (int d = 0; d < 7; ++d) g[d] = srow[d][gc];
            float med = select25(x, g);
            if (u >= 1) orow[2 * u - 1] = (med - mean) * inv;
        }
        {   // even pixel: global col 2u, lone sorted column smem 2u+6
            int gc = (2 * u + 6 > 517) ? 517 : 2 * u + 6;
            float g[7];
            #pragma unroll
            for (int d = 0; d < 7; ++d) g[d] = srow[d][gc];
            float med = select25(x, g);
            if (u <= 255) orow[2 * u] = (med - mean) * inv;
        }
    }
}

extern "C" void kernel_launch(void* const* d_in, const int* in_sizes, int n_in,
                              void* d_out, int out_size) {
    const float* img  = (const float*)d_in[0];
    const float* mask = (const float*)d_in[1];
    float* out = (float*)d_out;
    const int img_elems  = in_sizes[0];
    const int mask_elems = in_sizes[1];

    dim3 grid(512, 24);
    median7_kernel<<<grid, 256>>>(img, out);
    cudaMemcpyAsync(out + img_elems, mask, (size_t)mask_elems * sizeof(float),
                    cudaMemcpyDeviceToDevice);
}